// round 6
// baseline (speedup 1.0000x reference)
#include <cuda_runtime.h>
#include <math.h>

typedef unsigned long long ull;

#define Bb 64
#define Tt 1024
#define Ii 256
#define Hh 512
#define Gg 2048

// ---- scratch (device globals) ----
__device__ float g_xT[(size_t)Tt * Ii * Bb];
__device__ float g_XP[(size_t)Tt * Gg * Bb];
__device__ float g_OUT0[(size_t)Tt * Hh * Bb];
__device__ float g_h[2][Hh * Bb];
__device__ unsigned g_ready[128];

__device__ __forceinline__ ull ffma2(ull a, ull b, ull c) {
    ull d;
    asm("fma.rn.f32x2 %0, %1, %2, %3;" : "=l"(d) : "l"(a), "l"(b), "l"(c));
    return d;
}
__device__ __forceinline__ ull splat2(float v) {
    ull d;
    asm("mov.b64 %0, {%1, %1};" : "=l"(d) : "f"(v));
    return d;
}
__device__ __forceinline__ float sigf(float x) { return 1.0f / (1.0f + __expf(-x)); }
__device__ __forceinline__ unsigned ldacq(const unsigned* p) {
    unsigned v;
    asm volatile("ld.global.acquire.gpu.b32 %0, [%1];" : "=r"(v) : "l"(p));
    return v;
}
__device__ __forceinline__ void strel(unsigned* p, unsigned v) {
    asm volatile("st.global.release.gpu.b32 [%0], %1;" :: "l"(p), "r"(v));
}

// ---- transpose x[b][i][t] -> g_xT[t][i][b] ----
__global__ void k_trx(const float* __restrict__ x) {
    __shared__ float tile[32][33];
    int t0 = blockIdx.x * 32, b0 = blockIdx.y * 32, i = blockIdx.z;
    int tx = threadIdx.x, ty = threadIdx.y;
    tile[ty][tx] = x[((size_t)(b0 + ty) * Ii + i) * Tt + t0 + tx];
    __syncthreads();
    g_xT[((size_t)(t0 + ty) * Ii + i) * Bb + b0 + tx] = tile[tx][ty];
}

// ---- out transpose: g_OUT0[t][h][b] -> out[b][t][h] ----
__global__ void k_tro(float* __restrict__ out) {
    __shared__ float tile[32][33];
    int h0 = blockIdx.x * 32, b0 = blockIdx.y * 32, t = blockIdx.z;
    int tx = threadIdx.x, ty = threadIdx.y;
    tile[ty][tx] = g_OUT0[((size_t)t * Hh + h0 + ty) * Bb + b0 + tx];
    __syncthreads();
    out[((size_t)(b0 + ty) * Tt + t) * Hh + h0 + tx] = tile[tx][ty];
}

// ---- input GEMM: XP[t][g][b] = sum_k W[g][k]*X[t][k][b] + bih[g]+bhh[g] ----
__global__ void __launch_bounds__(256) k_gemm(const float* __restrict__ W,
                                              const float* __restrict__ bih,
                                              const float* __restrict__ bhh,
                                              const float* __restrict__ X, int K) {
    const int g0 = blockIdx.x * 128, t0 = blockIdx.y * 2;
    __shared__ float As[2][8][264];
    __shared__ float Bs[2][8][128];
    const int tid = threadIdx.x;
    const int rg = tid >> 4, cg = tid & 15;
    const int ar = tid >> 1, ak = (tid & 1) * 4;
    const int bkk = tid >> 5, bc = (tid & 31) * 4;
    const int btb = bc >> 6, bcb = bc & 63;
    const float* Arow = W + (size_t)(g0 + ar) * K + ak;
    const float* Bsrc = X + ((size_t)(t0 + btb) * K + bkk) * Bb + bcb;

    ull acc[8][4];
#pragma unroll
    for (int i = 0; i < 8; i++)
#pragma unroll
        for (int p = 0; p < 4; p++) acc[i][p] = 0ull;

    {
        float4 w4 = *(const float4*)(Arow);
#pragma unroll
        for (int jj = 0; jj < 4; jj++) {
            float v = ((const float*)&w4)[jj];
            *(float2*)&As[0][ak + jj][2 * ar] = make_float2(v, v);
        }
        *(float4*)&Bs[0][bkk][bc] = *(const float4*)(Bsrc);
    }
    __syncthreads();

    const int nk = K >> 3;
    for (int kc = 0; kc < nk; kc++) {
        const int cur = kc & 1;
        float4 w4n, b4n;
        if (kc + 1 < nk) {
            w4n = *(const float4*)(Arow + (kc + 1) * 8);
            b4n = *(const float4*)(Bsrc + (size_t)(kc + 1) * 8 * Bb);
        }
#pragma unroll
        for (int kk = 0; kk < 8; kk++) {
            ulonglong2 q0 = *(const ulonglong2*)&As[cur][kk][16 * rg];
            ulonglong2 q1 = *(const ulonglong2*)&As[cur][kk][16 * rg + 4];
            ulonglong2 q2 = *(const ulonglong2*)&As[cur][kk][16 * rg + 8];
            ulonglong2 q3 = *(const ulonglong2*)&As[cur][kk][16 * rg + 12];
            ulonglong2 u0 = *(const ulonglong2*)&Bs[cur][kk][8 * cg];
            ulonglong2 u1 = *(const ulonglong2*)&Bs[cur][kk][8 * cg + 4];
            ull a8[8] = {q0.x, q0.y, q1.x, q1.y, q2.x, q2.y, q3.x, q3.y};
            ull b4[4] = {u0.x, u0.y, u1.x, u1.y};
#pragma unroll
            for (int i = 0; i < 8; i++)
#pragma unroll
                for (int p = 0; p < 4; p++) acc[i][p] = ffma2(a8[i], b4[p], acc[i][p]);
        }
        if (kc + 1 < nk) {
            const int nxt = cur ^ 1;
#pragma unroll
            for (int jj = 0; jj < 4; jj++) {
                float v = ((const float*)&w4n)[jj];
                *(float2*)&As[nxt][ak + jj][2 * ar] = make_float2(v, v);
            }
            *(float4*)&Bs[nxt][bkk][bc] = b4n;
        }
        __syncthreads();
    }

#pragma unroll
    for (int i = 0; i < 8; i++) {
        const int grow = g0 + rg * 8 + i;
        const float bias = bih[grow] + bhh[grow];
#pragma unroll
        for (int p = 0; p < 4; p++) {
            float2 v = *(float2*)&acc[i][p];
            v.x += bias; v.y += bias;
            const int c = cg * 8 + 2 * p;
            *(float2*)(g_XP + ((size_t)(t0 + (c >> 6)) * Gg + grow) * Bb + (c & 63)) = v;
        }
    }
}

// ---- reset: flags + h0 ----
__global__ void k_reset() {
    int tid = blockIdx.x * blockDim.x + threadIdx.x;
    if (tid < 128) g_ready[tid] = 0u;
    if (tid < Hh * Bb) g_h[0][tid] = 0.0f;
}

// ---- persistent recurrence: 128 blocks x 256 thr, dataflow flag sync ----
// block j owns h-idx [4j,4j+4): gate row = q*512 + 4j + hh (q=gate, hh=0..3).
// thread: kq = tid>>6 (k-quarter role, rotated per block), b = tid&63.
__global__ void __launch_bounds__(256) k_rec(const float* __restrict__ Whh,
                                             float* __restrict__ slab,
                                             float* __restrict__ dout, int layer) {
    extern __shared__ float sm[];
    float* Wt = sm;              // [512][16]
    float* red = sm + 8192;      // [4][64][17]
    const int tid = threadIdx.x;
    const int j = blockIdx.x;
    const int kq = tid >> 6, b = tid & 63;
    const int lane = tid & 31;
    const int kqe = (kq + j) & 3;     // rotated quarter -> pipeline across blocks
    const int kb = kqe * 128;
    const int hh = kq;

    for (int idx = tid; idx < 8192; idx += 256) {
        int r = idx & 15, k = idx >> 4;
        Wt[idx] = Whh[(size_t)((r >> 2) * Hh + j * 4 + (r & 3)) * Hh + k];
    }
    __syncthreads();

    float c_reg = 0.0f;
    const int hi = j * 4 + hh;
    float* outHid = dout + (size_t)Bb * Tt * Hh + (size_t)layer * Bb * Hh;
    float* outCell = outHid + 2 * (size_t)Bb * Hh;
    const unsigned* myflag = &g_ready[kqe * 32 + lane];

    for (int t = 0; t < Tt; t++) {
        const float* hR = g_h[t & 1];
        const float* xpt = g_XP + (size_t)t * Gg * Bb;

        // prefetch xp for activation (hidden behind flag wait)
        float xv[4];
#pragma unroll
        for (int q = 0; q < 4; q++)
            xv[q] = __ldcg(&xpt[(size_t)(q * Hh + hi) * Bb + b]);

        // wait: our k-quarter's 32 producers published step t (one coalesced poll/lane)
        while (ldacq(myflag) < (unsigned)t) { }
        __syncwarp();

        ull acc[8];
#pragma unroll
        for (int i = 0; i < 8; i++) acc[i] = 0ull;

        float hv[2][8];
#pragma unroll
        for (int u = 0; u < 8; u++)
            hv[0][u] = __ldcg(&hR[(kb + u) * Bb + b]);

        for (int gblk = 0; gblk < 16; gblk++) {
            const int cur = gblk & 1;
            if (gblk < 15) {
#pragma unroll
                for (int u = 0; u < 8; u++)
                    hv[cur ^ 1][u] = __ldcg(&hR[(kb + (gblk + 1) * 8 + u) * Bb + b]);
            }
#pragma unroll
            for (int u = 0; u < 8; u++) {
                ull hp = splat2(hv[cur][u]);
                const float* wk = Wt + (kb + gblk * 8 + u) * 16;
#pragma unroll
                for (int i = 0; i < 4; i++) {
                    ulonglong2 w2 = *(const ulonglong2*)(wk + 4 * i);
                    acc[2 * i] = ffma2(w2.x, hp, acc[2 * i]);
                    acc[2 * i + 1] = ffma2(w2.y, hp, acc[2 * i + 1]);
                }
            }
        }

        // store partials: red[kq][b][r] (slot by kq; sum over slots is k-complete)
        {
            float* rp = red + (kq * 64 + b) * 17;
            const float* af = (const float*)acc;
#pragma unroll
            for (int r = 0; r < 16; r++) rp[r] = af[r];
        }
        __syncthreads();

        // activation: thread (hh, b)
        float gv[4];
#pragma unroll
        for (int q = 0; q < 4; q++) {
            float s = xv[q];
#pragma unroll
            for (int k2 = 0; k2 < 4; k2++) s += red[(k2 * 64 + b) * 17 + q * 4 + hh];
            gv[q] = s;
        }
        float ig = sigf(gv[0]), fg = sigf(gv[1]);
        float gg = tanhf(gv[2]), og = sigf(gv[3]);
        c_reg = fg * c_reg + ig * gg;
        float hval = og * tanhf(c_reg);
        __stcg(&g_h[(t + 1) & 1][hi * Bb + b], hval);
        __stcg(&slab[((size_t)t * Hh + hi) * Bb + b], hval);
        if (t == Tt - 1) {
            outHid[(size_t)b * Hh + hi] = hval;
            outCell[(size_t)b * Hh + hi] = c_reg;
        }

        // publish: order h stores before flag release
        __threadfence();
        __syncthreads();
        if (tid == 0) strel(&g_ready[j], (unsigned)(t + 1));
    }
}

extern "C" void kernel_launch(void* const* d_in, const int* in_sizes, int n_in,
                              void* d_out, int out_size) {
    const float* x = (const float*)d_in[0];
    const float* Wih0 = (const float*)d_in[1];
    const float* Whh0 = (const float*)d_in[2];
    const float* bih0 = (const float*)d_in[3];
    const float* bhh0 = (const float*)d_in[4];
    const float* Wih1 = (const float*)d_in[5];
    const float* Whh1 = (const float*)d_in[6];
    const float* bih1 = (const float*)d_in[7];
    const float* bhh1 = (const float*)d_in[8];
    float* out = (float*)d_out;

    float *xT, *out0;
    cudaGetSymbolAddress((void**)&xT, g_xT);
    cudaGetSymbolAddress((void**)&out0, g_OUT0);

    const int recSmem = (8192 + 4 * 64 * 17) * 4;
    cudaFuncSetAttribute(k_rec, cudaFuncAttributeMaxDynamicSharedMemorySize, recSmem);

    dim3 thr32(32, 32);

    // layer 0
    k_trx<<<dim3(Tt / 32, Bb / 32, Ii), thr32>>>(x);
    k_gemm<<<dim3(Gg / 128, Tt / 2), 256>>>(Wih0, bih0, bhh0, xT, Ii);
    k_reset<<<128, 256>>>();
    k_rec<<<128, 256, recSmem>>>(Whh0, out0, out, 0);

    // layer 1
    k_gemm<<<dim3(Gg / 128, Tt / 2), 256>>>(Wih1, bih1, bhh1, out0, Hh);
    k_reset<<<128, 256>>>();
    k_rec<<<128, 256, recSmem>>>(Whh1, out0, out, 1);

    // final transpose to out[b][t][h]
    k_tro<<<dim3(Hh / 32, Bb / 32, Tt), thr32>>>(out);
}

// round 7
// speedup vs baseline: 1.0484x; 1.0484x over previous
#include <cuda_runtime.h>
#include <math.h>

typedef unsigned long long ull;

#define Bb 64
#define Tt 1024
#define Ii 256
#define Hh 512
#define Gg 2048

// ---- scratch (device globals) ----
__device__ float g_xT[(size_t)Tt * Ii * Bb];
__device__ float g_XP[(size_t)Tt * Gg * Bb];
__device__ float g_OUT0[(size_t)Tt * Hh * Bb];
__device__ float g_h[2][Hh * Bb];
__device__ unsigned g_ctr[256];   // 4 counters at [0],[64],[128],[192] (256B apart)

__device__ __forceinline__ ull ffma2(ull a, ull b, ull c) {
    ull d;
    asm("fma.rn.f32x2 %0, %1, %2, %3;" : "=l"(d) : "l"(a), "l"(b), "l"(c));
    return d;
}
__device__ __forceinline__ ull splat2(float v) {
    ull d;
    asm("mov.b64 %0, {%1, %1};" : "=l"(d) : "f"(v));
    return d;
}
__device__ __forceinline__ float sigf(float x) { return 1.0f / (1.0f + __expf(-x)); }
__device__ __forceinline__ unsigned ldacq(const unsigned* p) {
    unsigned v;
    asm volatile("ld.global.acquire.gpu.b32 %0, [%1];" : "=r"(v) : "l"(p));
    return v;
}
__device__ __forceinline__ void redrel(unsigned* p) {
    asm volatile("red.release.gpu.global.add.u32 [%0], 1;" :: "l"(p));
}

// ---- transpose x[b][i][t] -> g_xT[t][i][b] ----
__global__ void k_trx(const float* __restrict__ x) {
    __shared__ float tile[32][33];
    int t0 = blockIdx.x * 32, b0 = blockIdx.y * 32, i = blockIdx.z;
    int tx = threadIdx.x, ty = threadIdx.y;
    tile[ty][tx] = x[((size_t)(b0 + ty) * Ii + i) * Tt + t0 + tx];
    __syncthreads();
    g_xT[((size_t)(t0 + ty) * Ii + i) * Bb + b0 + tx] = tile[tx][ty];
}

// ---- out transpose: g_OUT0[t][h][b] -> out[b][t][h] ----
__global__ void k_tro(float* __restrict__ out) {
    __shared__ float tile[32][33];
    int h0 = blockIdx.x * 32, b0 = blockIdx.y * 32, t = blockIdx.z;
    int tx = threadIdx.x, ty = threadIdx.y;
    tile[ty][tx] = g_OUT0[((size_t)t * Hh + h0 + ty) * Bb + b0 + tx];
    __syncthreads();
    out[((size_t)(b0 + ty) * Tt + t) * Hh + h0 + tx] = tile[tx][ty];
}

// ---- input GEMM: XP[t][g][b] = sum_k W[g][k]*X[t][k][b] + bih[g]+bhh[g] ----
__global__ void __launch_bounds__(256) k_gemm(const float* __restrict__ W,
                                              const float* __restrict__ bih,
                                              const float* __restrict__ bhh,
                                              const float* __restrict__ X, int K) {
    const int g0 = blockIdx.x * 128, t0 = blockIdx.y * 2;
    __shared__ float As[2][8][264];
    __shared__ float Bs[2][8][128];
    const int tid = threadIdx.x;
    const int rg = tid >> 4, cg = tid & 15;
    const int ar = tid >> 1, ak = (tid & 1) * 4;
    const int bkk = tid >> 5, bc = (tid & 31) * 4;
    const int btb = bc >> 6, bcb = bc & 63;
    const float* Arow = W + (size_t)(g0 + ar) * K + ak;
    const float* Bsrc = X + ((size_t)(t0 + btb) * K + bkk) * Bb + bcb;

    ull acc[8][4];
#pragma unroll
    for (int i = 0; i < 8; i++)
#pragma unroll
        for (int p = 0; p < 4; p++) acc[i][p] = 0ull;

    {
        float4 w4 = *(const float4*)(Arow);
#pragma unroll
        for (int jj = 0; jj < 4; jj++) {
            float v = ((const float*)&w4)[jj];
            *(float2*)&As[0][ak + jj][2 * ar] = make_float2(v, v);
        }
        *(float4*)&Bs[0][bkk][bc] = *(const float4*)(Bsrc);
    }
    __syncthreads();

    const int nk = K >> 3;
    for (int kc = 0; kc < nk; kc++) {
        const int cur = kc & 1;
        float4 w4n, b4n;
        if (kc + 1 < nk) {
            w4n = *(const float4*)(Arow + (kc + 1) * 8);
            b4n = *(const float4*)(Bsrc + (size_t)(kc + 1) * 8 * Bb);
        }
#pragma unroll
        for (int kk = 0; kk < 8; kk++) {
            ulonglong2 q0 = *(const ulonglong2*)&As[cur][kk][16 * rg];
            ulonglong2 q1 = *(const ulonglong2*)&As[cur][kk][16 * rg + 4];
            ulonglong2 q2 = *(const ulonglong2*)&As[cur][kk][16 * rg + 8];
            ulonglong2 q3 = *(const ulonglong2*)&As[cur][kk][16 * rg + 12];
            ulonglong2 u0 = *(const ulonglong2*)&Bs[cur][kk][8 * cg];
            ulonglong2 u1 = *(const ulonglong2*)&Bs[cur][kk][8 * cg + 4];
            ull a8[8] = {q0.x, q0.y, q1.x, q1.y, q2.x, q2.y, q3.x, q3.y};
            ull b4[4] = {u0.x, u0.y, u1.x, u1.y};
#pragma unroll
            for (int i = 0; i < 8; i++)
#pragma unroll
                for (int p = 0; p < 4; p++) acc[i][p] = ffma2(a8[i], b4[p], acc[i][p]);
        }
        if (kc + 1 < nk) {
            const int nxt = cur ^ 1;
#pragma unroll
            for (int jj = 0; jj < 4; jj++) {
                float v = ((const float*)&w4n)[jj];
                *(float2*)&As[nxt][ak + jj][2 * ar] = make_float2(v, v);
            }
            *(float4*)&Bs[nxt][bkk][bc] = b4n;
        }
        __syncthreads();
    }

#pragma unroll
    for (int i = 0; i < 8; i++) {
        const int grow = g0 + rg * 8 + i;
        const float bias = bih[grow] + bhh[grow];
#pragma unroll
        for (int p = 0; p < 4; p++) {
            float2 v = *(float2*)&acc[i][p];
            v.x += bias; v.y += bias;
            const int c = cg * 8 + 2 * p;
            *(float2*)(g_XP + ((size_t)(t0 + (c >> 6)) * Gg + grow) * Bb + (c & 63)) = v;
        }
    }
}

// ---- reset: counters + h0 ----
__global__ void k_reset() {
    int tid = blockIdx.x * blockDim.x + threadIdx.x;
    if (tid < 256) g_ctr[tid] = 0u;
    if (tid < Hh * Bb) g_h[0][tid] = 0.0f;
}

// ---- persistent recurrence: 128 blocks x 256 thr ----
// block j owns h-idx [4j,4j+4): gate row = q*512 + 4j + hh (q=gate, hh=0..3).
// thread roles: kq = tid>>6 (k-quarter for GEMM; also hh for activation), b = tid&63.
// sync: 4 spread counters; block j arrives at ctr[j&3] with red.release;
//       tid 0..3 poll one counter each (acquire), then __syncthreads.
__global__ void __launch_bounds__(256) k_rec(const float* __restrict__ Whh,
                                             float* __restrict__ slab,
                                             float* __restrict__ dout, int layer) {
    extern __shared__ float sm[];
    float* Wt = sm;              // [512][16]
    float* red = sm + 8192;      // [4][64][17]
    const int tid = threadIdx.x;
    const int j = blockIdx.x;
    const int kq = tid >> 6, b = tid & 63;
    const int kb = kq * 128;
    const int hh = kq;

    for (int idx = tid; idx < 8192; idx += 256) {
        int r = idx & 15, k = idx >> 4;
        Wt[idx] = Whh[(size_t)((r >> 2) * Hh + j * 4 + (r & 3)) * Hh + k];
    }
    __syncthreads();

    float c_reg = 0.0f;
    const int hi = j * 4 + hh;
    float* outHid = dout + (size_t)Bb * Tt * Hh + (size_t)layer * Bb * Hh;
    float* outCell = outHid + 2 * (size_t)Bb * Hh;
    unsigned* myctr = &g_ctr[(j & 3) * 64];

    for (int t = 0; t < Tt; t++) {
        const float* hR = g_h[t & 1];
        const float* xpt = g_XP + (size_t)t * Gg * Bb;

        // prefetch xp for activation (independent of the wait)
        float xv[4];
#pragma unroll
        for (int q = 0; q < 4; q++)
            xv[q] = __ldcg(&xpt[(size_t)(q * Hh + hi) * Bb + b]);

        // wait: all 128 blocks published step t-1 (4 pollers, one counter each)
        if (t > 0) {
            if (tid < 4) {
                const unsigned tgt = 32u * (unsigned)t;
                const unsigned* cp = &g_ctr[tid * 64];
                while (ldacq(cp) < tgt) { }
            }
            __syncthreads();
        }

        ull acc[8];
#pragma unroll
        for (int i = 0; i < 8; i++) acc[i] = 0ull;

        float hv[2][8];
#pragma unroll
        for (int u = 0; u < 8; u++)
            hv[0][u] = __ldcg(&hR[(kb + u) * Bb + b]);

        for (int gblk = 0; gblk < 16; gblk++) {
            const int cur = gblk & 1;
            if (gblk < 15) {
#pragma unroll
                for (int u = 0; u < 8; u++)
                    hv[cur ^ 1][u] = __ldcg(&hR[(kb + (gblk + 1) * 8 + u) * Bb + b]);
            }
#pragma unroll
            for (int u = 0; u < 8; u++) {
                ull hp = splat2(hv[cur][u]);
                const float* wk = Wt + (kb + gblk * 8 + u) * 16;
#pragma unroll
                for (int i = 0; i < 4; i++) {
                    ulonglong2 w2 = *(const ulonglong2*)(wk + 4 * i);
                    acc[2 * i] = ffma2(w2.x, hp, acc[2 * i]);
                    acc[2 * i + 1] = ffma2(w2.y, hp, acc[2 * i + 1]);
                }
            }
        }

        // store partials: red[kq][b][r]
        {
            float* rp = red + (kq * 64 + b) * 17;
            const float* af = (const float*)acc;
#pragma unroll
            for (int r = 0; r < 16; r++) rp[r] = af[r];
        }
        __syncthreads();

        // activation: thread (hh, b)
        float gv[4];
#pragma unroll
        for (int q = 0; q < 4; q++) {
            float s = xv[q];
#pragma unroll
            for (int k2 = 0; k2 < 4; k2++) s += red[(k2 * 64 + b) * 17 + q * 4 + hh];
            gv[q] = s;
        }
        float ig = sigf(gv[0]), fg = sigf(gv[1]);
        float gg = tanhf(gv[2]), og = sigf(gv[3]);
        c_reg = fg * c_reg + ig * gg;
        float hval = og * tanhf(c_reg);
        __stcg(&g_h[(t + 1) & 1][hi * Bb + b], hval);
        __stcg(&slab[((size_t)t * Hh + hi) * Bb + b], hval);
        if (t == Tt - 1) {
            outHid[(size_t)b * Hh + hi] = hval;
            outCell[(size_t)b * Hh + hi] = c_reg;
        }

        // publish: bar.sync (intra-CTA order) + release-RMW by tid 0
        __syncthreads();
        if (tid == 0) redrel(myctr);
    }
}

extern "C" void kernel_launch(void* const* d_in, const int* in_sizes, int n_in,
                              void* d_out, int out_size) {
    const float* x = (const float*)d_in[0];
    const float* Wih0 = (const float*)d_in[1];
    const float* Whh0 = (const float*)d_in[2];
    const float* bih0 = (const float*)d_in[3];
    const float* bhh0 = (const float*)d_in[4];
    const float* Wih1 = (const float*)d_in[5];
    const float* Whh1 = (const float*)d_in[6];
    const float* bih1 = (const float*)d_in[7];
    const float* bhh1 = (const float*)d_in[8];
    float* out = (float*)d_out;

    float *xT, *out0;
    cudaGetSymbolAddress((void**)&xT, g_xT);
    cudaGetSymbolAddress((void**)&out0, g_OUT0);

    const int recSmem = (8192 + 4 * 64 * 17) * 4;
    cudaFuncSetAttribute(k_rec, cudaFuncAttributeMaxDynamicSharedMemorySize, recSmem);

    dim3 thr32(32, 32);

    // layer 0
    k_trx<<<dim3(Tt / 32, Bb / 32, Ii), thr32>>>(x);
    k_gemm<<<dim3(Gg / 128, Tt / 2), 256>>>(Wih0, bih0, bhh0, xT, Ii);
    k_reset<<<128, 256>>>();
    k_rec<<<128, 256, recSmem>>>(Whh0, out0, out, 0);

    // layer 1
    k_gemm<<<dim3(Gg / 128, Tt / 2), 256>>>(Wih1, bih1, bhh1, out0, Hh);
    k_reset<<<128, 256>>>();
    k_rec<<<128, 256, recSmem>>>(Whh1, out0, out, 1);

    // final transpose to out[b][t][h]
    k_tro<<<dim3(Hh / 32, Bb / 32, Tt), thr32>>>(out);
}

// round 9
// speedup vs baseline: 2.0244x; 1.9309x over previous
#include <cuda_runtime.h>
#include <math.h>

typedef unsigned long long ull;

#define Bb 64
#define Tt 1024
#define Ii 256
#define Hh 512
#define Gg 2048

// ---- scratch (device globals) ----
__device__ float g_xT[(size_t)Tt * Ii * Bb];
__device__ float g_XP[(size_t)Tt * Gg * Bb];
__device__ float g_OUT0[(size_t)Tt * Hh * Bb];
__device__ float g_h[2][Hh * Bb];
__device__ unsigned g_ctr[256];   // 4 counters at [0],[64],[128],[192] (256B apart)

__device__ __forceinline__ ull ffma2(ull a, ull b, ull c) {
    ull d;
    asm("fma.rn.f32x2 %0, %1, %2, %3;" : "=l"(d) : "l"(a), "l"(b), "l"(c));
    return d;
}
__device__ __forceinline__ ull splat2(float v) {
    ull d;
    asm("mov.b64 %0, {%1, %1};" : "=l"(d) : "f"(v));
    return d;
}
__device__ __forceinline__ float sigf(float x) { return 1.0f / (1.0f + __expf(-x)); }
__device__ __forceinline__ unsigned ldacq(const unsigned* p) {
    unsigned v;
    asm volatile("ld.global.acquire.gpu.b32 %0, [%1];" : "=r"(v) : "l"(p));
    return v;
}
__device__ __forceinline__ void redrel(unsigned* p) {
    asm volatile("red.release.gpu.global.add.u32 [%0], 1;" :: "l"(p));
}

// ---- transpose x[b][i][t] -> g_xT[t][i][b] ----
__global__ void k_trx(const float* __restrict__ x) {
    __shared__ float tile[32][33];
    int t0 = blockIdx.x * 32, b0 = blockIdx.y * 32, i = blockIdx.z;
    int tx = threadIdx.x, ty = threadIdx.y;
    tile[ty][tx] = x[((size_t)(b0 + ty) * Ii + i) * Tt + t0 + tx];
    __syncthreads();
    g_xT[((size_t)(t0 + ty) * Ii + i) * Bb + b0 + tx] = tile[tx][ty];
}

// ---- out transpose: g_OUT0[t][h][b] -> out[b][t][h] ----
__global__ void k_tro(float* __restrict__ out) {
    __shared__ float tile[32][33];
    int h0 = blockIdx.x * 32, b0 = blockIdx.y * 32, t = blockIdx.z;
    int tx = threadIdx.x, ty = threadIdx.y;
    tile[ty][tx] = g_OUT0[((size_t)t * Hh + h0 + ty) * Bb + b0 + tx];
    __syncthreads();
    out[((size_t)(b0 + ty) * Tt + t) * Hh + h0 + tx] = tile[tx][ty];
}

// ---- input GEMM: XP[t][g][b] = sum_k W[g][k]*X[t][k][b] + bih[g]+bhh[g] ----
__global__ void __launch_bounds__(256) k_gemm(const float* __restrict__ W,
                                              const float* __restrict__ bih,
                                              const float* __restrict__ bhh,
                                              const float* __restrict__ X, int K) {
    const int g0 = blockIdx.x * 128, t0 = blockIdx.y * 2;
    __shared__ float As[2][8][264];
    __shared__ float Bs[2][8][128];
    const int tid = threadIdx.x;
    const int rg = tid >> 4, cg = tid & 15;
    const int ar = tid >> 1, ak = (tid & 1) * 4;
    const int bkk = tid >> 5, bc = (tid & 31) * 4;
    const int btb = bc >> 6, bcb = bc & 63;
    const float* Arow = W + (size_t)(g0 + ar) * K + ak;
    const float* Bsrc = X + ((size_t)(t0 + btb) * K + bkk) * Bb + bcb;

    ull acc[8][4];
#pragma unroll
    for (int i = 0; i < 8; i++)
#pragma unroll
        for (int p = 0; p < 4; p++) acc[i][p] = 0ull;

    {
        float4 w4 = *(const float4*)(Arow);
#pragma unroll
        for (int jj = 0; jj < 4; jj++) {
            float v = ((const float*)&w4)[jj];
            *(float2*)&As[0][ak + jj][2 * ar] = make_float2(v, v);
        }
        *(float4*)&Bs[0][bkk][bc] = *(const float4*)(Bsrc);
    }
    __syncthreads();

    const int nk = K >> 3;
    for (int kc = 0; kc < nk; kc++) {
        const int cur = kc & 1;
        float4 w4n, b4n;
        if (kc + 1 < nk) {
            w4n = *(const float4*)(Arow + (kc + 1) * 8);
            b4n = *(const float4*)(Bsrc + (size_t)(kc + 1) * 8 * Bb);
        }
#pragma unroll
        for (int kk = 0; kk < 8; kk++) {
            ulonglong2 q0 = *(const ulonglong2*)&As[cur][kk][16 * rg];
            ulonglong2 q1 = *(const ulonglong2*)&As[cur][kk][16 * rg + 4];
            ulonglong2 q2 = *(const ulonglong2*)&As[cur][kk][16 * rg + 8];
            ulonglong2 q3 = *(const ulonglong2*)&As[cur][kk][16 * rg + 12];
            ulonglong2 u0 = *(const ulonglong2*)&Bs[cur][kk][8 * cg];
            ulonglong2 u1 = *(const ulonglong2*)&Bs[cur][kk][8 * cg + 4];
            ull a8[8] = {q0.x, q0.y, q1.x, q1.y, q2.x, q2.y, q3.x, q3.y};
            ull b4[4] = {u0.x, u0.y, u1.x, u1.y};
#pragma unroll
            for (int i = 0; i < 8; i++)
#pragma unroll
                for (int p = 0; p < 4; p++) acc[i][p] = ffma2(a8[i], b4[p], acc[i][p]);
        }
        if (kc + 1 < nk) {
            const int nxt = cur ^ 1;
#pragma unroll
            for (int jj = 0; jj < 4; jj++) {
                float v = ((const float*)&w4n)[jj];
                *(float2*)&As[nxt][ak + jj][2 * ar] = make_float2(v, v);
            }
            *(float4*)&Bs[nxt][bkk][bc] = b4n;
        }
        __syncthreads();
    }

#pragma unroll
    for (int i = 0; i < 8; i++) {
        const int grow = g0 + rg * 8 + i;
        const float bias = bih[grow] + bhh[grow];
#pragma unroll
        for (int p = 0; p < 4; p++) {
            float2 v = *(float2*)&acc[i][p];
            v.x += bias; v.y += bias;
            const int c = cg * 8 + 2 * p;
            *(float2*)(g_XP + ((size_t)(t0 + (c >> 6)) * Gg + grow) * Bb + (c & 63)) = v;
        }
    }
}

// ---- reset: counters + h0 ----
__global__ void k_reset() {
    int tid = blockIdx.x * blockDim.x + threadIdx.x;
    if (tid < 256) g_ctr[tid] = 0u;
    if (tid < Hh * Bb) g_h[0][tid] = 0.0f;
}

// ---- persistent recurrence: 128 blocks x 512 thr ----
// block j owns h-idx [4j,4j+4): gate row = q*512 + 4j + hh (q=gate, hh=0..3).
// GEMM roles: ko = tid>>6 (k-eighth, 64 k each), b = tid&63; 16 rows per thread.
// Activation roles (tid<256): hh = tid>>6, b = tid&63.
// sync: 4 spread counters; block j arrives at ctr[j&3] with red.release;
//       tid 0..3 poll one counter each (acquire), then __syncthreads.
__global__ void __launch_bounds__(512, 1) k_rec(const float* __restrict__ Whh,
                                                float* __restrict__ slab,
                                                float* __restrict__ dout, int layer) {
    extern __shared__ float sm[];
    float* Wt = sm;              // [512 k][16 r]
    float* red = sm + 8192;      // [8 slot][64 b][17]
    const int tid = threadIdx.x;
    const int j = blockIdx.x;
    const int ko = tid >> 6, b = tid & 63;
    const int kb = ko * 64;
    const int hh = ko & 3;       // activation role (valid for tid<256)

    for (int idx = tid; idx < 8192; idx += 512) {
        int r = idx & 15, k = idx >> 4;
        Wt[idx] = Whh[(size_t)((r >> 2) * Hh + j * 4 + (r & 3)) * Hh + k];
    }
    __syncthreads();

    float c_reg = 0.0f;
    const int hi = j * 4 + hh;
    float* outHid = dout + (size_t)Bb * Tt * Hh + (size_t)layer * Bb * Hh;
    float* outCell = outHid + 2 * (size_t)Bb * Hh;
    unsigned* myctr = &g_ctr[(j & 3) * 64];

    for (int t = 0; t < Tt; t++) {
        const float* hR = g_h[t & 1];
        const float* xpt = g_XP + (size_t)t * Gg * Bb;

        // prefetch xp for activation (independent of the wait)
        float xv[4];
        if (tid < 256) {
#pragma unroll
            for (int q = 0; q < 4; q++)
                xv[q] = __ldcg(&xpt[(size_t)(q * Hh + hi) * Bb + b]);
        }

        // wait: all 128 blocks published step t-1 (4 pollers, one counter each)
        if (t > 0) {
            if (tid < 4) {
                const unsigned tgt = 32u * (unsigned)t;
                const unsigned* cp = &g_ctr[tid * 64];
                while (ldacq(cp) < tgt) { }
            }
            __syncthreads();
        }

        ull acc[8];
#pragma unroll
        for (int i = 0; i < 8; i++) acc[i] = 0ull;

        float hv[2][8];
#pragma unroll
        for (int u = 0; u < 8; u++)
            hv[0][u] = __ldcg(&hR[(kb + u) * Bb + b]);

#pragma unroll
        for (int kc = 0; kc < 8; kc++) {
            const int cur = kc & 1;
            if (kc < 7) {
#pragma unroll
                for (int u = 0; u < 8; u++)
                    hv[cur ^ 1][u] = __ldcg(&hR[(kb + (kc + 1) * 8 + u) * Bb + b]);
            }
#pragma unroll
            for (int u = 0; u < 8; u++) {
                ull hp = splat2(hv[cur][u]);
                const float* wk = Wt + (kb + kc * 8 + u) * 16;
#pragma unroll
                for (int i = 0; i < 4; i++) {
                    ulonglong2 w2 = *(const ulonglong2*)(wk + 4 * i);
                    acc[2 * i] = ffma2(w2.x, hp, acc[2 * i]);
                    acc[2 * i + 1] = ffma2(w2.y, hp, acc[2 * i + 1]);
                }
            }
        }

        // store partials: red[ko][b][r]
        {
            float* rp = red + (ko * 64 + b) * 17;
            const float* af = (const float*)acc;
#pragma unroll
            for (int r = 0; r < 16; r++) rp[r] = af[r];
        }
        __syncthreads();

        if (tid < 256) {
            // activation: thread (hh, b)
            float gv[4];
#pragma unroll
            for (int q = 0; q < 4; q++) {
                float s = xv[q];
#pragma unroll
                for (int k2 = 0; k2 < 8; k2++) s += red[(k2 * 64 + b) * 17 + q * 4 + hh];
                gv[q] = s;
            }
            float ig = sigf(gv[0]), fg = sigf(gv[1]);
            float gg = tanhf(gv[2]), og = sigf(gv[3]);
            c_reg = fg * c_reg + ig * gg;
            float hval = og * tanhf(c_reg);
            __stcg(&g_h[(t + 1) & 1][hi * Bb + b], hval);
            __stcg(&slab[((size_t)t * Hh + hi) * Bb + b], hval);
            if (t == Tt - 1) {
                outHid[(size_t)b * Hh + hi] = hval;
                outCell[(size_t)b * Hh + hi] = c_reg;
            }
        }

        // publish: bar.sync (intra-CTA order) + release-RMW by tid 0
        __syncthreads();
        if (tid == 0) redrel(myctr);
    }
}

extern "C" void kernel_launch(void* const* d_in, const int* in_sizes, int n_in,
                              void* d_out, int out_size) {
    const float* x = (const float*)d_in[0];
    const float* Wih0 = (const float*)d_in[1];
    const float* Whh0 = (const float*)d_in[2];
    const float* bih0 = (const float*)d_in[3];
    const float* bhh0 = (const float*)d_in[4];
    const float* Wih1 = (const float*)d_in[5];
    const float* Whh1 = (const float*)d_in[6];
    const float* bih1 = (const float*)d_in[7];
    const float* bhh1 = (const float*)d_in[8];
    float* out = (float*)d_out;

    float *xT, *out0;
    cudaGetSymbolAddress((void**)&xT, g_xT);
    cudaGetSymbolAddress((void**)&out0, g_OUT0);

    const int recSmem = (8192 + 8 * 64 * 17) * 4;
    cudaFuncSetAttribute(k_rec, cudaFuncAttributeMaxDynamicSharedMemorySize, recSmem);

    dim3 thr32(32, 32);

    // layer 0
    k_trx<<<dim3(Tt / 32, Bb / 32, Ii), thr32>>>(x);
    k_gemm<<<dim3(Gg / 128, Tt / 2), 256>>>(Wih0, bih0, bhh0, xT, Ii);
    k_reset<<<128, 256>>>();
    k_rec<<<128, 512, recSmem>>>(Whh0, out0, out, 0);

    // layer 1
    k_gemm<<<dim3(Gg / 128, Tt / 2), 256>>>(Wih1, bih1, bhh1, out0, Hh);
    k_reset<<<128, 256>>>();
    k_rec<<<128, 512, recSmem>>>(Whh1, out0, out, 1);

    // final transpose to out[b][t][h]
    k_tro<<<dim3(Hh / 32, Bb / 32, Tt), thr32>>>(out);
}

// round 10
// speedup vs baseline: 2.1337x; 1.0540x over previous
#include <cuda_runtime.h>
#include <math.h>

typedef unsigned long long ull;

#define Bb 64
#define Tt 1024
#define Ii 256
#define Hh 512
#define Gg 2048

// ---- scratch (device globals) ----
__device__ float g_xT[(size_t)Tt * Ii * Bb];
__device__ float g_XP[(size_t)Tt * Gg * Bb];
__device__ float g_OUT0[(size_t)Tt * Hh * Bb];
__device__ float g_h[2][Hh * Bb];
__device__ unsigned g_ctr[512];   // 8 chunk counters at [c*64], 256B apart

__device__ __forceinline__ ull ffma2(ull a, ull b, ull c) {
    ull d;
    asm("fma.rn.f32x2 %0, %1, %2, %3;" : "=l"(d) : "l"(a), "l"(b), "l"(c));
    return d;
}
__device__ __forceinline__ ull splat2(float v) {
    ull d;
    asm("mov.b64 %0, {%1, %1};" : "=l"(d) : "f"(v));
    return d;
}
__device__ __forceinline__ float tanhapx(float x) {
    float y;
    asm("tanh.approx.f32 %0, %1;" : "=f"(y) : "f"(x));
    return y;
}
__device__ __forceinline__ float sigapx(float x) {
    return 0.5f * tanhapx(0.5f * x) + 0.5f;
}
__device__ __forceinline__ unsigned ldacq(const unsigned* p) {
    unsigned v;
    asm volatile("ld.global.acquire.gpu.b32 %0, [%1];" : "=r"(v) : "l"(p));
    return v;
}
__device__ __forceinline__ void redrel(unsigned* p) {
    asm volatile("red.release.gpu.global.add.u32 [%0], 1;" :: "l"(p));
}

// ---- transpose x[b][i][t] -> g_xT[t][i][b] ----
__global__ void k_trx(const float* __restrict__ x) {
    __shared__ float tile[32][33];
    int t0 = blockIdx.x * 32, b0 = blockIdx.y * 32, i = blockIdx.z;
    int tx = threadIdx.x, ty = threadIdx.y;
    tile[ty][tx] = x[((size_t)(b0 + ty) * Ii + i) * Tt + t0 + tx];
    __syncthreads();
    g_xT[((size_t)(t0 + ty) * Ii + i) * Bb + b0 + tx] = tile[tx][ty];
}

// ---- out transpose: g_OUT0[t][h][b] -> out[b][t][h] ----
__global__ void k_tro(float* __restrict__ out) {
    __shared__ float tile[32][33];
    int h0 = blockIdx.x * 32, b0 = blockIdx.y * 32, t = blockIdx.z;
    int tx = threadIdx.x, ty = threadIdx.y;
    tile[ty][tx] = g_OUT0[((size_t)t * Hh + h0 + ty) * Bb + b0 + tx];
    __syncthreads();
    out[((size_t)(b0 + ty) * Tt + t) * Hh + h0 + tx] = tile[tx][ty];
}

// ---- input GEMM: XP[t][g][b] = sum_k W[g][k]*X[t][k][b] + bih[g]+bhh[g] ----
__global__ void __launch_bounds__(256) k_gemm(const float* __restrict__ W,
                                              const float* __restrict__ bih,
                                              const float* __restrict__ bhh,
                                              const float* __restrict__ X, int K) {
    const int g0 = blockIdx.x * 128, t0 = blockIdx.y * 2;
    __shared__ float As[2][8][264];
    __shared__ float Bs[2][8][128];
    const int tid = threadIdx.x;
    const int rg = tid >> 4, cg = tid & 15;
    const int ar = tid >> 1, ak = (tid & 1) * 4;
    const int bkk = tid >> 5, bc = (tid & 31) * 4;
    const int btb = bc >> 6, bcb = bc & 63;
    const float* Arow = W + (size_t)(g0 + ar) * K + ak;
    const float* Bsrc = X + ((size_t)(t0 + btb) * K + bkk) * Bb + bcb;

    ull acc[8][4];
#pragma unroll
    for (int i = 0; i < 8; i++)
#pragma unroll
        for (int p = 0; p < 4; p++) acc[i][p] = 0ull;

    {
        float4 w4 = *(const float4*)(Arow);
#pragma unroll
        for (int jj = 0; jj < 4; jj++) {
            float v = ((const float*)&w4)[jj];
            *(float2*)&As[0][ak + jj][2 * ar] = make_float2(v, v);
        }
        *(float4*)&Bs[0][bkk][bc] = *(const float4*)(Bsrc);
    }
    __syncthreads();

    const int nk = K >> 3;
    for (int kc = 0; kc < nk; kc++) {
        const int cur = kc & 1;
        float4 w4n, b4n;
        if (kc + 1 < nk) {
            w4n = *(const float4*)(Arow + (kc + 1) * 8);
            b4n = *(const float4*)(Bsrc + (size_t)(kc + 1) * 8 * Bb);
        }
#pragma unroll
        for (int kk = 0; kk < 8; kk++) {
            ulonglong2 q0 = *(const ulonglong2*)&As[cur][kk][16 * rg];
            ulonglong2 q1 = *(const ulonglong2*)&As[cur][kk][16 * rg + 4];
            ulonglong2 q2 = *(const ulonglong2*)&As[cur][kk][16 * rg + 8];
            ulonglong2 q3 = *(const ulonglong2*)&As[cur][kk][16 * rg + 12];
            ulonglong2 u0 = *(const ulonglong2*)&Bs[cur][kk][8 * cg];
            ulonglong2 u1 = *(const ulonglong2*)&Bs[cur][kk][8 * cg + 4];
            ull a8[8] = {q0.x, q0.y, q1.x, q1.y, q2.x, q2.y, q3.x, q3.y};
            ull b4[4] = {u0.x, u0.y, u1.x, u1.y};
#pragma unroll
            for (int i = 0; i < 8; i++)
#pragma unroll
                for (int p = 0; p < 4; p++) acc[i][p] = ffma2(a8[i], b4[p], acc[i][p]);
        }
        if (kc + 1 < nk) {
            const int nxt = cur ^ 1;
#pragma unroll
            for (int jj = 0; jj < 4; jj++) {
                float v = ((const float*)&w4n)[jj];
                *(float2*)&As[nxt][ak + jj][2 * ar] = make_float2(v, v);
            }
            *(float4*)&Bs[nxt][bkk][bc] = b4n;
        }
        __syncthreads();
    }

#pragma unroll
    for (int i = 0; i < 8; i++) {
        const int grow = g0 + rg * 8 + i;
        const float bias = bih[grow] + bhh[grow];
#pragma unroll
        for (int p = 0; p < 4; p++) {
            float2 v = *(float2*)&acc[i][p];
            v.x += bias; v.y += bias;
            const int c = cg * 8 + 2 * p;
            *(float2*)(g_XP + ((size_t)(t0 + (c >> 6)) * Gg + grow) * Bb + (c & 63)) = v;
        }
    }
}

// ---- reset: counters + h0 ----
__global__ void k_reset() {
    int tid = blockIdx.x * blockDim.x + threadIdx.x;
    if (tid < 512) g_ctr[tid] = 0u;
    if (tid < Hh * Bb) g_h[0][tid] = 0.0f;
}

// ---- persistent recurrence: 128 blocks x 512 thr, per-chunk dataflow sync ----
// block j owns h-idx [4j,4j+4): gate row = q*512 + 4j + hh (q=gate, hh=0..3).
// GEMM roles: ko = tid>>6 (k-eighth, 64 k each), b = tid&63; 16 rows per thread.
// sync: 8 chunk counters (ctr[c*64]); producer block j arrives at ctr[j>>4]
//       with red.release; each warp's lane 0 polls only chunk ko (acquire),
//       so warps start as soon as THEIR h-chunk is published.
__global__ void __launch_bounds__(512, 1) k_rec(const float* __restrict__ Whh,
                                                float* __restrict__ slab,
                                                float* __restrict__ dout, int layer) {
    extern __shared__ float sm[];
    float* Wt = sm;              // [512 k][16 r]
    float* red = sm + 8192;      // [8 slot][64 b][17]
    const int tid = threadIdx.x;
    const int j = blockIdx.x;
    const int ko = tid >> 6, b = tid & 63;
    const int kb = ko * 64;
    const int hh = ko & 3;       // activation role (valid for tid<256)

    for (int idx = tid; idx < 8192; idx += 512) {
        int r = idx & 15, k = idx >> 4;
        Wt[idx] = Whh[(size_t)((r >> 2) * Hh + j * 4 + (r & 3)) * Hh + k];
    }
    __syncthreads();

    float c_reg = 0.0f;
    const int hi = j * 4 + hh;
    float* outHid = dout + (size_t)Bb * Tt * Hh + (size_t)layer * Bb * Hh;
    float* outCell = outHid + 2 * (size_t)Bb * Hh;
    unsigned* myctr = &g_ctr[(j >> 4) * 64];
    const unsigned* pollctr = &g_ctr[ko * 64];

    for (int t = 0; t < Tt; t++) {
        const float* hR = g_h[t & 1];
        const float* xpt = g_XP + (size_t)t * Gg * Bb;

        // prefetch xp for activation (independent of the wait)
        float xv[4];
        if (tid < 256) {
#pragma unroll
            for (int q = 0; q < 4; q++)
                xv[q] = __ldcg(&xpt[(size_t)(q * Hh + hi) * Bb + b]);
        }

        // per-warp wait: chunk ko's 16 producers published step t
        {
            const unsigned tgt = 16u * (unsigned)t;
            if ((tid & 31) == 0) {
                while (ldacq(pollctr) < tgt) { }
            }
            __syncwarp();
        }

        ull acc[8];
#pragma unroll
        for (int i = 0; i < 8; i++) acc[i] = 0ull;

        float hv[2][8];
#pragma unroll
        for (int u = 0; u < 8; u++)
            hv[0][u] = __ldcg(&hR[(kb + u) * Bb + b]);

#pragma unroll
        for (int kc = 0; kc < 8; kc++) {
            const int cur = kc & 1;
            if (kc < 7) {
#pragma unroll
                for (int u = 0; u < 8; u++)
                    hv[cur ^ 1][u] = __ldcg(&hR[(kb + (kc + 1) * 8 + u) * Bb + b]);
            }
#pragma unroll
            for (int u = 0; u < 8; u++) {
                ull hp = splat2(hv[cur][u]);
                const float* wk = Wt + (kb + kc * 8 + u) * 16;
#pragma unroll
                for (int i = 0; i < 4; i++) {
                    ulonglong2 w2 = *(const ulonglong2*)(wk + 4 * i);
                    acc[2 * i] = ffma2(w2.x, hp, acc[2 * i]);
                    acc[2 * i + 1] = ffma2(w2.y, hp, acc[2 * i + 1]);
                }
            }
        }

        // store partials: red[ko][b][r]
        {
            float* rp = red + (ko * 64 + b) * 17;
            const float* af = (const float*)acc;
#pragma unroll
            for (int r = 0; r < 16; r++) rp[r] = af[r];
        }
        __syncthreads();

        if (tid < 256) {
            // activation: thread (hh, b)
            float gv[4];
#pragma unroll
            for (int q = 0; q < 4; q++) {
                float s = xv[q];
#pragma unroll
                for (int k2 = 0; k2 < 8; k2++) s += red[(k2 * 64 + b) * 17 + q * 4 + hh];
                gv[q] = s;
            }
            float ig = sigapx(gv[0]), fg = sigapx(gv[1]);
            float gg = tanhapx(gv[2]), og = sigapx(gv[3]);
            c_reg = fg * c_reg + ig * gg;
            float hval = og * tanhapx(c_reg);
            __stcg(&g_h[(t + 1) & 1][hi * Bb + b], hval);
            __stcg(&slab[((size_t)t * Hh + hi) * Bb + b], hval);
            if (t == Tt - 1) {
                outHid[(size_t)b * Hh + hi] = hval;
                outCell[(size_t)b * Hh + hi] = c_reg;
            }
        }

        // publish: bar.sync (intra-CTA order) + release-RMW by tid 0
        __syncthreads();
        if (tid == 0) redrel(myctr);
    }
}

extern "C" void kernel_launch(void* const* d_in, const int* in_sizes, int n_in,
                              void* d_out, int out_size) {
    const float* x = (const float*)d_in[0];
    const float* Wih0 = (const float*)d_in[1];
    const float* Whh0 = (const float*)d_in[2];
    const float* bih0 = (const float*)d_in[3];
    const float* bhh0 = (const float*)d_in[4];
    const float* Wih1 = (const float*)d_in[5];
    const float* Whh1 = (const float*)d_in[6];
    const float* bih1 = (const float*)d_in[7];
    const float* bhh1 = (const float*)d_in[8];
    float* out = (float*)d_out;

    float *xT, *out0;
    cudaGetSymbolAddress((void**)&xT, g_xT);
    cudaGetSymbolAddress((void**)&out0, g_OUT0);

    const int recSmem = (8192 + 8 * 64 * 17) * 4;
    cudaFuncSetAttribute(k_rec, cudaFuncAttributeMaxDynamicSharedMemorySize, recSmem);

    dim3 thr32(32, 32);

    // layer 0
    k_trx<<<dim3(Tt / 32, Bb / 32, Ii), thr32>>>(x);
    k_gemm<<<dim3(Gg / 128, Tt / 2), 256>>>(Wih0, bih0, bhh0, xT, Ii);
    k_reset<<<128, 256>>>();
    k_rec<<<128, 512, recSmem>>>(Whh0, out0, out, 0);

    // layer 1
    k_gemm<<<dim3(Gg / 128, Tt / 2), 256>>>(Wih1, bih1, bhh1, out0, Hh);
    k_reset<<<128, 256>>>();
    k_rec<<<128, 512, recSmem>>>(Whh1, out0, out, 1);

    // final transpose to out[b][t][h]
    k_tro<<<dim3(Hh / 32, Bb / 32, Tt), thr32>>>(out);
}